// round 1
// baseline (speedup 1.0000x reference)
#include <cuda_runtime.h>

// Problem constants (AFM_42984032698906): B=256, N=64, d=64
constexpr int Bn = 256;
constexpr int Nn = 64;
constexpr int Dn = 64;
constexpr int SROW = 68;           // smem row stride in floats (16B-aligned, de-conflicted)
constexpr float NEG_SLOPE = 0.01f;

// One CTA per (b, i). 128 threads.
//  1) fill smem: E[j][d] = emb[b,j,d]; G[e][d] = W[e,d]*emb[b,i,d]
//     (and fused: write value[b,i,j,:] = emb[b,j,:]*emb[b,i,:] to gmem)
//  2) register-tiled GEMM: qk[j][e] = sum_d E[j][d]*G[e][d]
//  3) logits[j] = sum_e aW[e]*leakyrelu(qk[j][e] + wb[e]); shfl reduce over e
//  4) warp 0: softmax over j, write alphas[b,i,:]
__global__ __launch_bounds__(128)
void afm_kernel(const float* __restrict__ emb,
                const float* __restrict__ wW,
                const float* __restrict__ wb,
                const float* __restrict__ aW,
                float* __restrict__ outA,   // [B,N,N]
                float* __restrict__ outV)   // [B,N,N,D]
{
    const int i  = blockIdx.x;
    const int b  = blockIdx.y;
    const int tx = threadIdx.x;

    __shared__ float sE[Nn * SROW];
    __shared__ float sG[Dn * SROW];
    __shared__ float slog[Nn];

    const float* embB = emb + (size_t)b * Nn * Dn;
    const float* embI = embB + (size_t)i * Dn;

    // ---- Phase 1: fill shared tiles; fused value write ----
    {
        const int row = tx >> 1;           // 0..63
        const int c0  = (tx & 1) * 32;     // half-row of 32 floats
        const float4* eR = reinterpret_cast<const float4*>(embB + row * Dn + c0);
        const float4* wR = reinterpret_cast<const float4*>(wW   + row * Dn + c0);
        const float4* iR = reinterpret_cast<const float4*>(embI + c0);
        float4* sER = reinterpret_cast<float4*>(sE + row * SROW + c0);
        float4* sGR = reinterpret_cast<float4*>(sG + row * SROW + c0);
        float4* oV  = reinterpret_cast<float4*>(
            outV + ((((size_t)b * Nn + i) * Nn + row) * Dn + c0));
        #pragma unroll
        for (int k = 0; k < 8; k++) {
            float4 ev = eR[k];
            float4 wv = wR[k];
            float4 iv = iR[k];
            sER[k] = ev;
            sGR[k] = make_float4(wv.x * iv.x, wv.y * iv.y, wv.z * iv.z, wv.w * iv.w);
            oV[k]  = make_float4(ev.x * iv.x, ev.y * iv.y, ev.z * iv.z, ev.w * iv.w);
        }
    }
    __syncthreads();

    // ---- Phase 2: qk GEMM, 4x8 register tile per thread ----
    const int jg = tx >> 3;   // 0..15 -> j = r*16 + jg
    const int eg = tx & 7;    // 0..7  -> e = c*8  + eg

    float acc[4][8];
    #pragma unroll
    for (int r = 0; r < 4; r++)
        #pragma unroll
        for (int c = 0; c < 8; c++) acc[r][c] = 0.0f;

    #pragma unroll 4
    for (int d4 = 0; d4 < 16; d4++) {
        float4 av[4];
        float4 bv[8];
        #pragma unroll
        for (int r = 0; r < 4; r++)
            av[r] = *reinterpret_cast<const float4*>(sE + (r * 16 + jg) * SROW + d4 * 4);
        #pragma unroll
        for (int c = 0; c < 8; c++)
            bv[c] = *reinterpret_cast<const float4*>(sG + (c * 8 + eg) * SROW + d4 * 4);
        #pragma unroll
        for (int r = 0; r < 4; r++) {
            #pragma unroll
            for (int c = 0; c < 8; c++) {
                acc[r][c] = fmaf(av[r].x, bv[c].x, acc[r][c]);
                acc[r][c] = fmaf(av[r].y, bv[c].y, acc[r][c]);
                acc[r][c] = fmaf(av[r].z, bv[c].z, acc[r][c]);
                acc[r][c] = fmaf(av[r].w, bv[c].w, acc[r][c]);
            }
        }
    }

    // ---- Phase 3: bias + LeakyReLU + dot with aW, reduce over e-lanes ----
    float wbv[8], awv[8];
    #pragma unroll
    for (int c = 0; c < 8; c++) {
        const int e = c * 8 + eg;
        wbv[c] = wb[e];
        awv[c] = aW[e];
    }
    #pragma unroll
    for (int r = 0; r < 4; r++) {
        float p = 0.0f;
        #pragma unroll
        for (int c = 0; c < 8; c++) {
            float q = acc[r][c] + wbv[c];
            q = (q >= 0.0f) ? q : NEG_SLOPE * q;
            p = fmaf(awv[c], q, p);
        }
        // reduce over eg (lane bits 0..2)
        p += __shfl_xor_sync(0xffffffffu, p, 1);
        p += __shfl_xor_sync(0xffffffffu, p, 2);
        p += __shfl_xor_sync(0xffffffffu, p, 4);
        if (eg == 0) slog[r * 16 + jg] = p;
    }
    __syncthreads();

    // ---- Phase 4: softmax over 64 logits (warp 0), write alphas ----
    if (tx < 32) {
        float v0 = slog[tx];
        float v1 = slog[tx + 32];
        float m = fmaxf(v0, v1);
        #pragma unroll
        for (int msk = 16; msk >= 1; msk >>= 1)
            m = fmaxf(m, __shfl_xor_sync(0xffffffffu, m, msk));
        float e0 = __expf(v0 - m);
        float e1 = __expf(v1 - m);
        float s = e0 + e1;
        #pragma unroll
        for (int msk = 16; msk >= 1; msk >>= 1)
            s += __shfl_xor_sync(0xffffffffu, s, msk);
        const float inv = 1.0f / s;
        float* oa = outA + ((size_t)b * Nn + i) * Nn;
        oa[tx]      = e0 * inv;
        oa[tx + 32] = e1 * inv;
    }
}

extern "C" void kernel_launch(void* const* d_in, const int* in_sizes, int n_in,
                              void* d_out, int out_size)
{
    (void)in_sizes; (void)n_in; (void)out_size;
    const float* emb = (const float*)d_in[0];  // embeddings [256,64,64]
    const float* wW  = (const float*)d_in[1];  // [64,64] (out,in)
    const float* wb  = (const float*)d_in[2];  // [64]
    const float* aW  = (const float*)d_in[3];  // [64]
    // d_in[4] = a_b: constant shift, cancels in softmax (and is zero)

    float* out  = (float*)d_out;
    float* outA = out;                                   // alphas: B*N*N
    float* outV = out + (size_t)Bn * Nn * Nn;            // value:  B*N*N*D

    dim3 grid(Nn, Bn);   // (i, b)
    afm_kernel<<<grid, 128>>>(emb, wW, wb, aW, outA, outV);
}

// round 3
// speedup vs baseline: 1.6943x; 1.6943x over previous
#include <cuda_runtime.h>
#include <cuda_bf16.h>
#include <cstdint>

// Problem: B=256, N=64, d=64. Outputs concatenated: alphas [B,N,N,1] then value [B,N,N,64].
constexpr int Bn = 256;
constexpr int Nn = 64;
constexpr int Dn = 64;
constexpr float NEG_SLOPE = 0.01f;

constexpr int XROW = 68;   // fp32 smem row stride for emb[b]
constexpr int AROW = 72;   // bf16 smem row stride (144B: conflict-free for frag loads)

// dynamic smem layout (bytes)
constexpr int OFF_WB  = 0;                      // 64 f32
constexpr int OFF_AW  = 256;                    // 64 f32
constexpr int OFF_LOG = 512;                    // 128 f32
constexpr int OFF_SX  = 1024;                   // 64*68*4   = 17408
constexpr int OFF_AH  = OFF_SX + 17408;         // 128*72*2  = 18432
constexpr int OFF_AL  = OFF_AH + 18432;
constexpr int OFF_BH  = OFF_AL + 18432;         // 64*72*2   = 9216
constexpr int OFF_BL  = OFF_BH + 9216;
constexpr int SMEM_TOTAL = OFF_BL + 9216;       // 73728 B

static __device__ __forceinline__ void mma_bf16(float* c, const uint32_t* a, const uint32_t* b) {
    asm volatile(
        "mma.sync.aligned.m16n8k16.row.col.f32.bf16.bf16.f32 "
        "{%0,%1,%2,%3}, {%4,%5,%6,%7}, {%8,%9}, {%0,%1,%2,%3};"
        : "+f"(c[0]), "+f"(c[1]), "+f"(c[2]), "+f"(c[3])
        : "r"(a[0]), "r"(a[1]), "r"(a[2]), "r"(a[3]), "r"(b[0]), "r"(b[1]));
}

// split fp32 pair -> packed bf16x2 hi and bf16x2 lo
static __device__ __forceinline__ void split2(float a, float b, uint32_t& hi, uint32_t& lo) {
    __nv_bfloat16 ha = __float2bfloat16_rn(a);
    __nv_bfloat16 hb = __float2bfloat16_rn(b);
    float ra = a - __bfloat162float(ha);
    float rb = b - __bfloat162float(hb);
    __nv_bfloat162 h; h.x = ha; h.y = hb;
    __nv_bfloat162 l; l.x = __float2bfloat16_rn(ra); l.y = __float2bfloat16_rn(rb);
    hi = *reinterpret_cast<uint32_t*>(&h);
    lo = *reinterpret_cast<uint32_t*>(&l);
}

// One CTA: (b, i0=2*ib, i1=2*ib+1), 128 threads / 4 warps.
// Phase 1: smem fills (emb[b], W hi/lo planes, value rows hi/lo planes + fp32 gmem write)
// Phase 2: warp-level bf16 mma.sync, 3-term fp32 emulation: qk = A @ W^T
// Phase 3: bias + LeakyReLU + dot(aW) epilogue on fragments -> logits
// Phase 4: softmax per i over j, write alphas
__global__ __launch_bounds__(128, 3)
void afm_mma(const float* __restrict__ emb,
             const float* __restrict__ wW,
             const float* __restrict__ wb,
             const float* __restrict__ aW,
             float* __restrict__ outA,
             float* __restrict__ outV)
{
    extern __shared__ __align__(16) char smem[];
    const int ib  = blockIdx.x;   // 0..31
    const int b   = blockIdx.y;   // 0..255
    const int tx  = threadIdx.x;
    const int wid = tx >> 5;
    const int lid = tx & 31;
    const int g   = lid >> 2;     // 0..7
    const int q   = lid & 3;      // 0..3

    float* sWB  = reinterpret_cast<float*>(smem + OFF_WB);
    float* sAW  = reinterpret_cast<float*>(smem + OFF_AW);
    float* sLOG = reinterpret_cast<float*>(smem + OFF_LOG);
    float* sX   = reinterpret_cast<float*>(smem + OFF_SX);

    if (tx < 64) { sWB[tx] = wb[tx]; sAW[tx] = aW[tx]; }

    const int rhalf = tx >> 1;    // 0..63 (row)
    const int hf    = tx & 1;     // half-row of 32 elems

    const float* embB = emb + (size_t)b * Nn * Dn;

    // ---- emb[b] -> sX (padded fp32) ----
    {
        const float4* src = reinterpret_cast<const float4*>(embB + rhalf * Dn + hf * 32);
        float4* dst = reinterpret_cast<float4*>(sX + rhalf * XROW + hf * 32);
        #pragma unroll
        for (int k = 0; k < 8; k++) dst[k] = src[k];
    }

    // ---- W -> sBh / sBl (bf16 planes, padded) ----
    {
        const float4* src = reinterpret_cast<const float4*>(wW + rhalf * Dn + hf * 32);
        uint32_t hu[16], lu[16];
        #pragma unroll
        for (int k = 0; k < 8; k++) {
            float4 w4 = src[k];
            split2(w4.x, w4.y, hu[2 * k],     lu[2 * k]);
            split2(w4.z, w4.w, hu[2 * k + 1], lu[2 * k + 1]);
        }
        char* bh = smem + OFF_BH + rhalf * (AROW * 2) + hf * 64;
        char* bl = smem + OFF_BL + rhalf * (AROW * 2) + hf * 64;
        #pragma unroll
        for (int p = 0; p < 4; p++) {
            *reinterpret_cast<uint4*>(bh + p * 16) =
                make_uint4(hu[4 * p], hu[4 * p + 1], hu[4 * p + 2], hu[4 * p + 3]);
            *reinterpret_cast<uint4*>(bl + p * 16) =
                make_uint4(lu[4 * p], lu[4 * p + 1], lu[4 * p + 2], lu[4 * p + 3]);
        }
    }
    __syncthreads();

    // ---- value rows -> gmem fp32 + sAh / sAl bf16 planes ----
    #pragma unroll
    for (int L = 0; L < 2; L++) {
        const int iGlob = 2 * ib + L;
        const int row   = L * 64 + rhalf;
        const float4* xj = reinterpret_cast<const float4*>(sX + rhalf * XROW + hf * 32);
        const float4* xi = reinterpret_cast<const float4*>(sX + iGlob * XROW + hf * 32);
        float4* oV = reinterpret_cast<float4*>(
            outV + ((((size_t)b * Nn + iGlob) * Nn + rhalf) * Dn + hf * 32));
        uint32_t hu[16], lu[16];
        #pragma unroll
        for (int k = 0; k < 8; k++) {
            float4 a4 = xj[k];
            float4 b4 = xi[k];
            float4 v = make_float4(a4.x * b4.x, a4.y * b4.y, a4.z * b4.z, a4.w * b4.w);
            oV[k] = v;
            split2(v.x, v.y, hu[2 * k],     lu[2 * k]);
            split2(v.z, v.w, hu[2 * k + 1], lu[2 * k + 1]);
        }
        char* ah = smem + OFF_AH + row * (AROW * 2) + hf * 64;
        char* al = smem + OFF_AL + row * (AROW * 2) + hf * 64;
        #pragma unroll
        for (int p = 0; p < 4; p++) {
            *reinterpret_cast<uint4*>(ah + p * 16) =
                make_uint4(hu[4 * p], hu[4 * p + 1], hu[4 * p + 2], hu[4 * p + 3]);
            *reinterpret_cast<uint4*>(al + p * 16) =
                make_uint4(lu[4 * p], lu[4 * p + 1], lu[4 * p + 2], lu[4 * p + 3]);
        }
    }
    __syncthreads();

    // ---- warp-level GEMM: D[128x64] = A @ B^T, 3-term bf16 emulation ----
    // warp w owns M rows [32w, 32w+32): m-tiles of 16; 8 n-tiles of 8; 4 k-steps of 16.
    float acc[2][8][4];
    #pragma unroll
    for (int mt = 0; mt < 2; mt++)
        #pragma unroll
        for (int nt = 0; nt < 8; nt++)
            #pragma unroll
            for (int r = 0; r < 4; r++) acc[mt][nt][r] = 0.0f;

    const int wrow = wid * 32;

    #pragma unroll
    for (int ks = 0; ks < 4; ks++) {
        const int kc = ks * 16 + 2 * q;   // bf16 col of the pair this thread loads
        uint32_t ah[2][4], al[2][4];
        #pragma unroll
        for (int mt = 0; mt < 2; mt++) {
            const int r0 = wrow + mt * 16 + g;
            const char* baseH = smem + OFF_AH;
            const char* baseL = smem + OFF_AL;
            ah[mt][0] = *reinterpret_cast<const uint32_t*>(baseH + (r0      * AROW + kc)     * 2);
            ah[mt][1] = *reinterpret_cast<const uint32_t*>(baseH + ((r0 + 8)* AROW + kc)     * 2);
            ah[mt][2] = *reinterpret_cast<const uint32_t*>(baseH + (r0      * AROW + kc + 8) * 2);
            ah[mt][3] = *reinterpret_cast<const uint32_t*>(baseH + ((r0 + 8)* AROW + kc + 8) * 2);
            al[mt][0] = *reinterpret_cast<const uint32_t*>(baseL + (r0      * AROW + kc)     * 2);
            al[mt][1] = *reinterpret_cast<const uint32_t*>(baseL + ((r0 + 8)* AROW + kc)     * 2);
            al[mt][2] = *reinterpret_cast<const uint32_t*>(baseL + (r0      * AROW + kc + 8) * 2);
            al[mt][3] = *reinterpret_cast<const uint32_t*>(baseL + ((r0 + 8)* AROW + kc + 8) * 2);
        }
        uint32_t bh[8][2], bl[8][2];
        #pragma unroll
        for (int nt = 0; nt < 8; nt++) {
            const int n = nt * 8 + g;
            const char* baseH = smem + OFF_BH;
            const char* baseL = smem + OFF_BL;
            bh[nt][0] = *reinterpret_cast<const uint32_t*>(baseH + (n * AROW + kc)     * 2);
            bh[nt][1] = *reinterpret_cast<const uint32_t*>(baseH + (n * AROW + kc + 8) * 2);
            bl[nt][0] = *reinterpret_cast<const uint32_t*>(baseL + (n * AROW + kc)     * 2);
            bl[nt][1] = *reinterpret_cast<const uint32_t*>(baseL + (n * AROW + kc + 8) * 2);
        }
        #pragma unroll
        for (int nt = 0; nt < 8; nt++) {
            #pragma unroll
            for (int mt = 0; mt < 2; mt++) {
                mma_bf16(acc[mt][nt], ah[mt], bh[nt]);
                mma_bf16(acc[mt][nt], ah[mt], bl[nt]);
                mma_bf16(acc[mt][nt], al[mt], bh[nt]);
            }
        }
    }

    // ---- epilogue: logits ----
    float wb0[8], wb1[8], aw0[8], aw1[8];
    #pragma unroll
    for (int nt = 0; nt < 8; nt++) {
        const int e0 = nt * 8 + 2 * q;
        wb0[nt] = sWB[e0];     wb1[nt] = sWB[e0 + 1];
        aw0[nt] = sAW[e0];     aw1[nt] = sAW[e0 + 1];
    }
    #pragma unroll
    for (int mt = 0; mt < 2; mt++) {
        #pragma unroll
        for (int half = 0; half < 2; half++) {
            float p = 0.0f;
            #pragma unroll
            for (int nt = 0; nt < 8; nt++) {
                float q0 = acc[mt][nt][half * 2 + 0] + wb0[nt];
                float q1 = acc[mt][nt][half * 2 + 1] + wb1[nt];
                q0 = (q0 >= 0.0f) ? q0 : NEG_SLOPE * q0;
                q1 = (q1 >= 0.0f) ? q1 : NEG_SLOPE * q1;
                p = fmaf(aw0[nt], q0, p);
                p = fmaf(aw1[nt], q1, p);
            }
            p += __shfl_xor_sync(0xffffffffu, p, 1);
            p += __shfl_xor_sync(0xffffffffu, p, 2);
            if (q == 0) sLOG[wrow + mt * 16 + half * 8 + g] = p;
        }
    }
    __syncthreads();

    // ---- softmax per i over 64 j's: warp 0 -> i0, warp 1 -> i1 ----
    if (wid < 2) {
        float v0 = sLOG[wid * 64 + lid];
        float v1 = sLOG[wid * 64 + lid + 32];
        float m = fmaxf(v0, v1);
        #pragma unroll
        for (int msk = 16; msk >= 1; msk >>= 1)
            m = fmaxf(m, __shfl_xor_sync(0xffffffffu, m, msk));
        float e0 = __expf(v0 - m);
        float e1 = __expf(v1 - m);
        float s = e0 + e1;
        #pragma unroll
        for (int msk = 16; msk >= 1; msk >>= 1)
            s += __shfl_xor_sync(0xffffffffu, s, msk);
        const float inv = 1.0f / s;
        const int iGlob = 2 * ib + wid;
        float* oa = outA + ((size_t)b * Nn + iGlob) * Nn;
        oa[lid]      = e0 * inv;
        oa[lid + 32] = e1 * inv;
    }
}

extern "C" void kernel_launch(void* const* d_in, const int* in_sizes, int n_in,
                              void* d_out, int out_size)
{
    (void)in_sizes; (void)n_in; (void)out_size;
    const float* emb = (const float*)d_in[0];
    const float* wW  = (const float*)d_in[1];
    const float* wb  = (const float*)d_in[2];
    const float* aW  = (const float*)d_in[3];
    // d_in[4] = a_b: constant shift, cancels in softmax

    float* out  = (float*)d_out;
    float* outA = out;
    float* outV = out + (size_t)Bn * Nn * Nn;

    cudaFuncSetAttribute(afm_mma, cudaFuncAttributeMaxDynamicSharedMemorySize, SMEM_TOTAL);
    dim3 grid(Nn / 2, Bn);
    afm_mma<<<grid, 128, SMEM_TOTAL>>>(emb, wW, wb, aW, outA, outV);
}

// round 4
// speedup vs baseline: 1.7351x; 1.0241x over previous
#include <cuda_runtime.h>
#include <cuda_bf16.h>
#include <cstdint>

// Problem: B=256, N=64, d=64. Outputs concatenated: alphas [B,N,N,1] then value [B,N,N,64].
constexpr int Bn = 256;
constexpr int Nn = 64;
constexpr int Dn = 64;
constexpr float NEG_SLOPE = 0.01f;

constexpr int XROW = 68;    // fp32 smem row stride for emb[b]

// dynamic smem layout (bytes)
constexpr int OFF_WB  = 0;                       // 64 f32
constexpr int OFF_AW  = 256;                     // 64 f32
constexpr int OFF_LOG = 512;                     // 128 f32
constexpr int OFF_SX  = 1024;                    // emb[b] natural: 64*68*4 = 17408
constexpr int OFF_SF  = OFF_SX + 17408;          // E frag table fp32: 4ks*64j*4q*16B = 16384
constexpr int OFF_SB  = OFF_SF + 16384;          // W frag table bf16 hi/lo interleaved: 16384
constexpr int SMEM_TOTAL = OFF_SB + 16384;       // 51200 B

static __device__ __forceinline__ void mma_bf16(float* c, const uint32_t* a, const uint32_t* b) {
    asm volatile(
        "mma.sync.aligned.m16n8k16.row.col.f32.bf16.bf16.f32 "
        "{%0,%1,%2,%3}, {%4,%5,%6,%7}, {%8,%9}, {%0,%1,%2,%3};"
        : "+f"(c[0]), "+f"(c[1]), "+f"(c[2]), "+f"(c[3])
        : "r"(a[0]), "r"(a[1]), "r"(a[2]), "r"(a[3]), "r"(b[0]), "r"(b[1]));
}

// split fp32 pair -> packed bf16x2 hi and bf16x2 lo
static __device__ __forceinline__ void split2(float a, float b, uint32_t& hi, uint32_t& lo) {
    __nv_bfloat16 ha = __float2bfloat16_rn(a);
    __nv_bfloat16 hb = __float2bfloat16_rn(b);
    float ra = a - __bfloat162float(ha);
    float rb = b - __bfloat162float(hb);
    __nv_bfloat162 h; h.x = ha; h.y = hb;
    __nv_bfloat162 l; l.x = __float2bfloat16_rn(ra); l.y = __float2bfloat16_rn(rb);
    hi = *reinterpret_cast<uint32_t*>(&h);
    lo = *reinterpret_cast<uint32_t*>(&l);
}

static __device__ __forceinline__ void stcs4(float* p, float4 v) {
    asm volatile("st.global.cs.v4.f32 [%0], {%1,%2,%3,%4};"
                 :: "l"(p), "f"(v.x), "f"(v.y), "f"(v.z), "f"(v.w) : "memory");
}

// One CTA: (b, i0=2*ib, i1=2*ib+1), 128 threads / 4 warps (warps 0,1 -> i0; 2,3 -> i1).
__global__ __launch_bounds__(128, 4)
void afm_mma(const float* __restrict__ emb,
             const float* __restrict__ wW,
             const float* __restrict__ wb,
             const float* __restrict__ aW,
             float* __restrict__ outA,
             float* __restrict__ outV)
{
    extern __shared__ __align__(16) char smem[];
    const int ib  = blockIdx.x;   // 0..31
    const int b   = blockIdx.y;   // 0..255
    const int tx  = threadIdx.x;
    const int wid = tx >> 5;
    const int lid = tx & 31;
    const int g   = lid >> 2;     // 0..7
    const int q   = lid & 3;      // 0..3

    float* sWB  = reinterpret_cast<float*>(smem + OFF_WB);
    float* sAW  = reinterpret_cast<float*>(smem + OFF_AW);
    float* sLOG = reinterpret_cast<float*>(smem + OFF_LOG);
    float* sX   = reinterpret_cast<float*>(smem + OFF_SX);

    if (tx < 64) { sWB[tx] = wb[tx]; sAW[tx] = aW[tx]; }

    const int jr = tx >> 1;       // row 0..63 this thread fills
    const int hf = tx & 1;        // which 32-col half

    const float* embB = emb + (size_t)b * Nn * Dn;

    // ---- fill: emb row -> registers, sX (natural), sF (fp32 frag table) ----
    float4 ereg[8];
    {
        const float4* src = reinterpret_cast<const float4*>(embB + jr * Dn + hf * 32);
        float4* dst = reinterpret_cast<float4*>(sX + jr * XROW + hf * 32);
        #pragma unroll
        for (int k = 0; k < 8; k++) { ereg[k] = src[k]; dst[k] = ereg[k]; }
        #pragma unroll
        for (int s = 0; s < 2; s++) {
            const int ks = 2 * hf + s;
            #pragma unroll
            for (int qq = 0; qq < 4; qq++) {
                float4 va = ereg[4 * s + (qq >> 1)];
                float4 vb = ereg[4 * s + 2 + (qq >> 1)];
                float ax = (qq & 1) ? va.z : va.x;
                float ay = (qq & 1) ? va.w : va.y;
                float bx = (qq & 1) ? vb.z : vb.x;
                float by = (qq & 1) ? vb.w : vb.y;
                *reinterpret_cast<float4*>(
                    smem + OFF_SF + (((ks * 64 + jr) * 4 + qq) << 4)) =
                    make_float4(ax, ay, bx, by);
            }
        }
    }

    // ---- fill: W row -> bf16 hi/lo splits -> sB frag table (interleaved) ----
    {
        const float4* src = reinterpret_cast<const float4*>(wW + jr * Dn + hf * 32);
        uint32_t hu[16], lu[16];
        #pragma unroll
        for (int k = 0; k < 8; k++) {
            float4 w4 = src[k];
            split2(w4.x, w4.y, hu[2 * k],     lu[2 * k]);
            split2(w4.z, w4.w, hu[2 * k + 1], lu[2 * k + 1]);
        }
        #pragma unroll
        for (int s = 0; s < 2; s++) {
            const int ks = 2 * hf + s;
            #pragma unroll
            for (int qq = 0; qq < 4; qq++) {
                const int c0 = 8 * s + qq;
                *reinterpret_cast<uint4*>(
                    smem + OFF_SB + (((ks * 64 + jr) * 4 + qq) << 4)) =
                    make_uint4(hu[c0], hu[c0 + 4], lu[c0], lu[c0 + 4]);
            }
        }
    }
    __syncthreads();

    // ---- value writes: value[b,i,jr,:] = ereg * x_i (fp32, streaming) ----
    #pragma unroll
    for (int L = 0; L < 2; L++) {
        const int iGlob = 2 * ib + L;
        const float4* xi = reinterpret_cast<const float4*>(sX + iGlob * XROW + hf * 32);
        float* oV = outV + ((((size_t)b * Nn + iGlob) * Nn + jr) * Dn + hf * 32);
        #pragma unroll
        for (int k = 0; k < 8; k++) {
            float4 x4 = xi[k];
            float4 e4 = ereg[k];
            stcs4(oV + 4 * k, make_float4(e4.x * x4.x, e4.y * x4.y, e4.z * x4.z, e4.w * x4.w));
        }
    }

    // ---- GEMM: D[128x64] = (E*x_i) @ W^T, 3-term bf16 emulation ----
    const int iW = 2 * ib + (wid >> 1);            // this warp's i
    const float* sXi = sX + iW * XROW;
    const int jb = (wid & 1) * 32 + g;             // E row base (j) for mt tiles

    float acc[2][8][4];
    #pragma unroll
    for (int mt = 0; mt < 2; mt++)
        #pragma unroll
        for (int nt = 0; nt < 8; nt++)
            #pragma unroll
            for (int r = 0; r < 4; r++) acc[mt][nt][r] = 0.0f;

    #pragma unroll
    for (int ks = 0; ks < 4; ks++) {
        const int kc = ks * 16 + 2 * q;
        const float2 xa = *reinterpret_cast<const float2*>(sXi + kc);
        const float2 xb = *reinterpret_cast<const float2*>(sXi + kc + 8);

        uint32_t ah[2][4], al[2][4];
        #pragma unroll
        for (int mt = 0; mt < 2; mt++) {
            const int j0 = jb + mt * 16;
            const float4 f0 = *reinterpret_cast<const float4*>(
                smem + OFF_SF + (((ks * 64 + j0) * 4 + q) << 4));
            const float4 f1 = *reinterpret_cast<const float4*>(
                smem + OFF_SF + (((ks * 64 + j0 + 8) * 4 + q) << 4));
            split2(f0.x * xa.x, f0.y * xa.y, ah[mt][0], al[mt][0]);
            split2(f1.x * xa.x, f1.y * xa.y, ah[mt][1], al[mt][1]);
            split2(f0.z * xb.x, f0.w * xb.y, ah[mt][2], al[mt][2]);
            split2(f1.z * xb.x, f1.w * xb.y, ah[mt][3], al[mt][3]);
        }
        #pragma unroll
        for (int nt = 0; nt < 8; nt++) {
            const uint4 bv = *reinterpret_cast<const uint4*>(
                smem + OFF_SB + (((ks * 64 + nt * 8 + g) * 4 + q) << 4));
            uint32_t bh[2] = {bv.x, bv.y};
            uint32_t bl[2] = {bv.z, bv.w};
            #pragma unroll
            for (int mt = 0; mt < 2; mt++) {
                mma_bf16(acc[mt][nt], ah[mt], bh);
                mma_bf16(acc[mt][nt], ah[mt], bl);
                mma_bf16(acc[mt][nt], al[mt], bh);
            }
        }
    }

    // ---- epilogue: bias + LeakyReLU + dot(aW) -> logits ----
    const int wrow = wid * 32;
    float wb0[8], wb1[8], aw0[8], aw1[8];
    #pragma unroll
    for (int nt = 0; nt < 8; nt++) {
        const int e0 = nt * 8 + 2 * q;
        wb0[nt] = sWB[e0];     wb1[nt] = sWB[e0 + 1];
        aw0[nt] = sAW[e0];     aw1[nt] = sAW[e0 + 1];
    }
    #pragma unroll
    for (int mt = 0; mt < 2; mt++) {
        #pragma unroll
        for (int half = 0; half < 2; half++) {
            float p = 0.0f;
            #pragma unroll
            for (int nt = 0; nt < 8; nt++) {
                float q0 = acc[mt][nt][half * 2 + 0] + wb0[nt];
                float q1 = acc[mt][nt][half * 2 + 1] + wb1[nt];
                q0 = (q0 >= 0.0f) ? q0 : NEG_SLOPE * q0;
                q1 = (q1 >= 0.0f) ? q1 : NEG_SLOPE * q1;
                p = fmaf(aw0[nt], q0, p);
                p = fmaf(aw1[nt], q1, p);
            }
            p += __shfl_xor_sync(0xffffffffu, p, 1);
            p += __shfl_xor_sync(0xffffffffu, p, 2);
            if (q == 0) sLOG[wrow + mt * 16 + half * 8 + g] = p;
        }
    }
    __syncthreads();

    // ---- softmax per i over 64 j's: warp 0 -> i0, warp 1 -> i1 ----
    if (wid < 2) {
        float v0 = sLOG[wid * 64 + lid];
        float v1 = sLOG[wid * 64 + lid + 32];
        float m = fmaxf(v0, v1);
        #pragma unroll
        for (int msk = 16; msk >= 1; msk >>= 1)
            m = fmaxf(m, __shfl_xor_sync(0xffffffffu, m, msk));
        float e0 = __expf(v0 - m);
        float e1 = __expf(v1 - m);
        float s = e0 + e1;
        #pragma unroll
        for (int msk = 16; msk >= 1; msk >>= 1)
            s += __shfl_xor_sync(0xffffffffu, s, msk);
        const float inv = 1.0f / s;
        const int iGlob = 2 * ib + wid;
        float* oa = outA + ((size_t)b * Nn + iGlob) * Nn;
        oa[lid]      = e0 * inv;
        oa[lid + 32] = e1 * inv;
    }
}

extern "C" void kernel_launch(void* const* d_in, const int* in_sizes, int n_in,
                              void* d_out, int out_size)
{
    (void)in_sizes; (void)n_in; (void)out_size;
    const float* emb = (const float*)d_in[0];
    const float* wW  = (const float*)d_in[1];
    const float* wb  = (const float*)d_in[2];
    const float* aW  = (const float*)d_in[3];
    // d_in[4] = a_b: constant shift, cancels in softmax

    float* out  = (float*)d_out;
    float* outA = out;
    float* outV = out + (size_t)Bn * Nn * Nn;

    cudaFuncSetAttribute(afm_mma, cudaFuncAttributeMaxDynamicSharedMemorySize, SMEM_TOTAL);
    dim3 grid(Nn / 2, Bn);
    afm_mma<<<grid, 128, SMEM_TOTAL>>>(emb, wW, wb, aW, outA, outV);
}

// round 5
// speedup vs baseline: 1.7906x; 1.0320x over previous
#include <cuda_runtime.h>
#include <cuda_bf16.h>
#include <cstdint>

// Problem: B=256, N=64, d=64. Outputs concatenated: alphas [B,N,N,1] then value [B,N,N,64].
constexpr int Bn = 256;
constexpr int Nn = 64;
constexpr int Dn = 64;
constexpr float NEG_SLOPE = 0.01f;

constexpr int XROW = 76;    // fp32 smem row stride; half-row offset 36 (bank de-conflicted fill)

// dynamic smem layout (bytes)
constexpr int OFF_WB  = 0;                       // 64 f32
constexpr int OFF_AW  = 256;                     // 64 f32
constexpr int OFF_LOG = 512;                     // 128 f32
constexpr int OFF_SX  = 1024;                    // emb[b]: 64*76*4 = 19456
constexpr int OFF_SF  = OFF_SX + 19456;          // E frag table fp32 (swizzled): 16384
constexpr int OFF_SB  = OFF_SF + 16384;          // W frag table bf16 hi/lo (swizzled): 16384
constexpr int SMEM_TOTAL = OFF_SB + 16384;       // 53248 B

static __device__ __forceinline__ void mma_bf16(float* c, const uint32_t* a, const uint32_t* b) {
    asm volatile(
        "mma.sync.aligned.m16n8k16.row.col.f32.bf16.bf16.f32 "
        "{%0,%1,%2,%3}, {%4,%5,%6,%7}, {%8,%9}, {%0,%1,%2,%3};"
        : "+f"(c[0]), "+f"(c[1]), "+f"(c[2]), "+f"(c[3])
        : "r"(a[0]), "r"(a[1]), "r"(a[2]), "r"(a[3]), "r"(b[0]), "r"(b[1]));
}

// split fp32 pair -> packed bf16x2 hi and bf16x2 lo
static __device__ __forceinline__ void split2(float a, float b, uint32_t& hi, uint32_t& lo) {
    __nv_bfloat16 ha = __float2bfloat16_rn(a);
    __nv_bfloat16 hb = __float2bfloat16_rn(b);
    float ra = a - __bfloat162float(ha);
    float rb = b - __bfloat162float(hb);
    __nv_bfloat162 h; h.x = ha; h.y = hb;
    __nv_bfloat162 l; l.x = __float2bfloat16_rn(ra); l.y = __float2bfloat16_rn(rb);
    hi = *reinterpret_cast<uint32_t*>(&h);
    lo = *reinterpret_cast<uint32_t*>(&l);
}

static __device__ __forceinline__ void stcs4(float* p, float4 v) {
    asm volatile("st.global.cs.v4.f32 [%0], {%1,%2,%3,%4};"
                 :: "l"(p), "f"(v.x), "f"(v.y), "f"(v.z), "f"(v.w) : "memory");
}

// swizzled byte offset of 16B unit (j*4+q) inside ks-block of a frag table.
// XOR term (((j&3)<<1)|hf(ks)) spreads fill-store phases across all 8 bank
// groups while permuting reads only within 128B lines (reads stay conflict-free).
static __device__ __forceinline__ uint32_t swzoff(int j, int q, int ks) {
    uint32_t u = (uint32_t)(j * 4 + q);
    uint32_t t = (((uint32_t)j & 3u) << 1) | (((uint32_t)ks >> 1) & 1u);
    return ((uint32_t)ks << 12) + ((u ^ t) << 4);
}

// One CTA: (b, i0=2*ib, i1=2*ib+1), 128 threads / 4 warps (warps 0,1 -> i0; 2,3 -> i1).
__global__ __launch_bounds__(128, 4)
void afm_mma(const float* __restrict__ emb,
             const float* __restrict__ wW,
             const float* __restrict__ wb,
             const float* __restrict__ aW,
             float* __restrict__ outA,
             float* __restrict__ outV)
{
    extern __shared__ __align__(16) char smem[];
    const int ib  = blockIdx.x;   // 0..31
    const int b   = blockIdx.y;   // 0..255
    const int tx  = threadIdx.x;
    const int wid = tx >> 5;
    const int lid = tx & 31;
    const int g   = lid >> 2;     // 0..7
    const int q   = lid & 3;      // 0..3

    float* sWB  = reinterpret_cast<float*>(smem + OFF_WB);
    float* sAW  = reinterpret_cast<float*>(smem + OFF_AW);
    float* sLOG = reinterpret_cast<float*>(smem + OFF_LOG);
    float* sX   = reinterpret_cast<float*>(smem + OFF_SX);

    if (tx < 64) { sWB[tx] = wb[tx]; sAW[tx] = aW[tx]; }

    const int jr = tx >> 1;       // row 0..63 this thread fills
    const int hf = tx & 1;        // which 32-col half

    const float* embB = emb + (size_t)b * Nn * Dn;

    // ---- fill: emb row -> registers, sX (padded), sF (swizzled fp32 frag table) ----
    float4 ereg[8];
    {
        const float4* src = reinterpret_cast<const float4*>(embB + jr * Dn + hf * 32);
        float4* dst = reinterpret_cast<float4*>(sX + jr * XROW + hf * 36);
        #pragma unroll
        for (int k = 0; k < 8; k++) { ereg[k] = src[k]; dst[k] = ereg[k]; }
        #pragma unroll
        for (int s = 0; s < 2; s++) {
            const int ks = 2 * hf + s;
            #pragma unroll
            for (int qq = 0; qq < 4; qq++) {
                float4 va = ereg[4 * s + (qq >> 1)];
                float4 vb = ereg[4 * s + 2 + (qq >> 1)];
                float ax = (qq & 1) ? va.z : va.x;
                float ay = (qq & 1) ? va.w : va.y;
                float bx = (qq & 1) ? vb.z : vb.x;
                float by = (qq & 1) ? vb.w : vb.y;
                *reinterpret_cast<float4*>(smem + OFF_SF + swzoff(jr, qq, ks)) =
                    make_float4(ax, ay, bx, by);
            }
        }
    }

    // ---- fill: W row -> bf16 hi/lo splits -> sB frag table (swizzled, interleaved) ----
    {
        const float4* src = reinterpret_cast<const float4*>(wW + jr * Dn + hf * 32);
        uint32_t hu[16], lu[16];
        #pragma unroll
        for (int k = 0; k < 8; k++) {
            float4 w4 = src[k];
            split2(w4.x, w4.y, hu[2 * k],     lu[2 * k]);
            split2(w4.z, w4.w, hu[2 * k + 1], lu[2 * k + 1]);
        }
        #pragma unroll
        for (int s = 0; s < 2; s++) {
            const int ks = 2 * hf + s;
            #pragma unroll
            for (int qq = 0; qq < 4; qq++) {
                const int c0 = 8 * s + qq;
                *reinterpret_cast<uint4*>(smem + OFF_SB + swzoff(jr, qq, ks)) =
                    make_uint4(hu[c0], hu[c0 + 4], lu[c0], lu[c0 + 4]);
            }
        }
    }
    __syncthreads();

    // ---- value writes: value[b,i,jr,:] = ereg * x_i (fp32, streaming) ----
    #pragma unroll
    for (int L = 0; L < 2; L++) {
        const int iGlob = 2 * ib + L;
        const float4* xi = reinterpret_cast<const float4*>(sX + iGlob * XROW + hf * 36);
        float* oV = outV + ((((size_t)b * Nn + iGlob) * Nn + jr) * Dn + hf * 32);
        #pragma unroll
        for (int k = 0; k < 8; k++) {
            float4 x4 = xi[k];
            float4 e4 = ereg[k];
            stcs4(oV + 4 * k, make_float4(e4.x * x4.x, e4.y * x4.y, e4.z * x4.z, e4.w * x4.w));
        }
    }

    // ---- GEMM: D[128x64] = (E*x_i) @ W^T, 3-term bf16 emulation ----
    const int iW = 2 * ib + (wid >> 1);            // this warp's i
    const float* sXi = sX + iW * XROW;
    const int jb = (wid & 1) * 32 + g;             // E row base (j) for mt tiles

    float acc[2][8][4];
    #pragma unroll
    for (int mt = 0; mt < 2; mt++)
        #pragma unroll
        for (int nt = 0; nt < 8; nt++)
            #pragma unroll
            for (int r = 0; r < 4; r++) acc[mt][nt][r] = 0.0f;

    #pragma unroll
    for (int ks = 0; ks < 4; ks++) {
        const int kc  = ks * 16 + 2 * q;
        const int kcp = kc + ((ks >= 2) ? 4 : 0);   // physical col in padded sX row
        const float2 xa = *reinterpret_cast<const float2*>(sXi + kcp);
        const float2 xb = *reinterpret_cast<const float2*>(sXi + kcp + 8);

        uint32_t ah[2][4], al[2][4];
        #pragma unroll
        for (int mt = 0; mt < 2; mt++) {
            const int j0 = jb + mt * 16;
            const float4 f0 = *reinterpret_cast<const float4*>(
                smem + OFF_SF + swzoff(j0, q, ks));
            const float4 f1 = *reinterpret_cast<const float4*>(
                smem + OFF_SF + swzoff(j0 + 8, q, ks));
            split2(f0.x * xa.x, f0.y * xa.y, ah[mt][0], al[mt][0]);
            split2(f1.x * xa.x, f1.y * xa.y, ah[mt][1], al[mt][1]);
            split2(f0.z * xb.x, f0.w * xb.y, ah[mt][2], al[mt][2]);
            split2(f1.z * xb.x, f1.w * xb.y, ah[mt][3], al[mt][3]);
        }
        #pragma unroll
        for (int nt = 0; nt < 8; nt++) {
            const uint4 bv = *reinterpret_cast<const uint4*>(
                smem + OFF_SB + swzoff(nt * 8 + g, q, ks));
            uint32_t bh[2] = {bv.x, bv.y};
            uint32_t bl[2] = {bv.z, bv.w};
            #pragma unroll
            for (int mt = 0; mt < 2; mt++) {
                mma_bf16(acc[mt][nt], ah[mt], bh);
                mma_bf16(acc[mt][nt], ah[mt], bl);
                mma_bf16(acc[mt][nt], al[mt], bh);
            }
        }
    }

    // ---- epilogue: bias + LeakyReLU + dot(aW) -> logits ----
    const int wrow = wid * 32;
    float wb0[8], wb1[8], aw0[8], aw1[8];
    #pragma unroll
    for (int nt = 0; nt < 8; nt++) {
        const int e0 = nt * 8 + 2 * q;
        wb0[nt] = sWB[e0];     wb1[nt] = sWB[e0 + 1];
        aw0[nt] = sAW[e0];     aw1[nt] = sAW[e0 + 1];
    }
    #pragma unroll
    for (int mt = 0; mt < 2; mt++) {
        #pragma unroll
        for (int half = 0; half < 2; half++) {
            float p = 0.0f;
            #pragma unroll
            for (int nt = 0; nt < 8; nt++) {
                float q0 = acc[mt][nt][half * 2 + 0] + wb0[nt];
                float q1 = acc[mt][nt][half * 2 + 1] + wb1[nt];
                q0 = (q0 >= 0.0f) ? q0 : NEG_SLOPE * q0;
                q1 = (q1 >= 0.0f) ? q1 : NEG_SLOPE * q1;
                p = fmaf(aw0[nt], q0, p);
                p = fmaf(aw1[nt], q1, p);
            }
            p += __shfl_xor_sync(0xffffffffu, p, 1);
            p += __shfl_xor_sync(0xffffffffu, p, 2);
            if (q == 0) sLOG[wrow + mt * 16 + half * 8 + g] = p;
        }
    }
    __syncthreads();

    // ---- softmax per i over 64 j's: warp 0 -> i0, warp 1 -> i1 ----
    if (wid < 2) {
        float v0 = sLOG[wid * 64 + lid];
        float v1 = sLOG[wid * 64 + lid + 32];
        float m = fmaxf(v0, v1);
        #pragma unroll
        for (int msk = 16; msk >= 1; msk >>= 1)
            m = fmaxf(m, __shfl_xor_sync(0xffffffffu, m, msk));
        float e0 = __expf(v0 - m);
        float e1 = __expf(v1 - m);
        float s = e0 + e1;
        #pragma unroll
        for (int msk = 16; msk >= 1; msk >>= 1)
            s += __shfl_xor_sync(0xffffffffu, s, msk);
        const float inv = 1.0f / s;
        const int iGlob = 2 * ib + wid;
        float* oa = outA + ((size_t)b * Nn + iGlob) * Nn;
        oa[lid]      = e0 * inv;
        oa[lid + 32] = e1 * inv;
    }
}

extern "C" void kernel_launch(void* const* d_in, const int* in_sizes, int n_in,
                              void* d_out, int out_size)
{
    (void)in_sizes; (void)n_in; (void)out_size;
    const float* emb = (const float*)d_in[0];
    const float* wW  = (const float*)d_in[1];
    const float* wb  = (const float*)d_in[2];
    const float* aW  = (const float*)d_in[3];
    // d_in[4] = a_b: constant shift, cancels in softmax

    float* out  = (float*)d_out;
    float* outA = out;
    float* outV = out + (size_t)Bn * Nn * Nn;

    cudaFuncSetAttribute(afm_mma, cudaFuncAttributeMaxDynamicSharedMemorySize, SMEM_TOTAL);
    dim3 grid(Nn / 2, Bn);
    afm_mma<<<grid, 128, SMEM_TOTAL>>>(emb, wW, wb, aW, outA, outV);
}

// round 6
// speedup vs baseline: 2.1686x; 1.2111x over previous
#include <cuda_runtime.h>
#include <cuda_bf16.h>
#include <cstdint>

// Problem: B=256, N=64, d=64. Outputs concatenated: alphas [B,N,N,1] then value [B,N,N,64].
constexpr int Bn = 256;
constexpr int Nn = 64;
constexpr int Dn = 64;
constexpr float NEG_SLOPE = 0.01f;

// dynamic smem layout (bytes)
constexpr int OFF_WB  = 0;                       // 64 f32
constexpr int OFF_AW  = 256;                     // 64 f32
constexpr int OFF_LOG = 512;                     // 256 f32 (4 i's x 64 logits)
constexpr int OFF_XI  = 1536;                    // 4 i-rows natural fp32, stride 72: 1152 B
constexpr int OFF_SF  = 2688;                    // E frag table fp32 (swizzled): 16384
constexpr int OFF_SB  = OFF_SF + 16384;          // W frag table bf16 hi/lo (swizzled): 16384
constexpr int SMEM_TOTAL = OFF_SB + 16384;       // 35456 B

static __device__ __forceinline__ void mma_bf16(float* c, const uint32_t* a, const uint32_t* b) {
    asm volatile(
        "mma.sync.aligned.m16n8k16.row.col.f32.bf16.bf16.f32 "
        "{%0,%1,%2,%3}, {%4,%5,%6,%7}, {%8,%9}, {%0,%1,%2,%3};"
        : "+f"(c[0]), "+f"(c[1]), "+f"(c[2]), "+f"(c[3])
        : "r"(a[0]), "r"(a[1]), "r"(a[2]), "r"(a[3]), "r"(b[0]), "r"(b[1]));
}

// split fp32 pair -> packed bf16x2 hi and bf16x2 lo
static __device__ __forceinline__ void split2(float a, float b, uint32_t& hi, uint32_t& lo) {
    __nv_bfloat16 ha = __float2bfloat16_rn(a);
    __nv_bfloat16 hb = __float2bfloat16_rn(b);
    float ra = a - __bfloat162float(ha);
    float rb = b - __bfloat162float(hb);
    __nv_bfloat162 h; h.x = ha; h.y = hb;
    __nv_bfloat162 l; l.x = __float2bfloat16_rn(ra); l.y = __float2bfloat16_rn(rb);
    hi = *reinterpret_cast<uint32_t*>(&h);
    lo = *reinterpret_cast<uint32_t*>(&l);
}

static __device__ __forceinline__ void stcs4(float* p, float4 v) {
    asm volatile("st.global.cs.v4.f32 [%0], {%1,%2,%3,%4};"
                 :: "l"(p), "f"(v.x), "f"(v.y), "f"(v.z), "f"(v.w) : "memory");
}

// swizzled byte offset of 16B unit (j*4+q) inside ks-block of a frag table.
static __device__ __forceinline__ uint32_t swzoff(int j, int q, int ks) {
    uint32_t u = (uint32_t)(j * 4 + q);
    uint32_t t = (((uint32_t)j & 3u) << 1) | (((uint32_t)ks >> 1) & 1u);
    return ((uint32_t)ks << 12) + ((u ^ t) << 4);
}

// One CTA: (b, i0..i3 = 4*ib..4*ib+3), 128 threads / 4 warps.
// Two GEMM passes; pass p: warps 0,1 -> i(2p), warps 2,3 -> i(2p+1).
__global__ __launch_bounds__(128, 4)
void afm_mma(const float* __restrict__ emb,
             const float* __restrict__ wW,
             const float* __restrict__ wb,
             const float* __restrict__ aW,
             float* __restrict__ outA,
             float* __restrict__ outV)
{
    extern __shared__ __align__(16) char smem[];
    const int ib  = blockIdx.x;   // 0..15
    const int b   = blockIdx.y;   // 0..255
    const int tx  = threadIdx.x;
    const int wid = tx >> 5;
    const int lid = tx & 31;
    const int g   = lid >> 2;     // 0..7
    const int q   = lid & 3;      // 0..3

    float* sWB  = reinterpret_cast<float*>(smem + OFF_WB);
    float* sAW  = reinterpret_cast<float*>(smem + OFF_AW);
    float* sLOG = reinterpret_cast<float*>(smem + OFF_LOG);
    float* sXI  = reinterpret_cast<float*>(smem + OFF_XI);

    if (tx < 64) { sWB[tx] = wb[tx]; sAW[tx] = aW[tx]; }

    const int jr = tx >> 1;       // row 0..63 this thread fills
    const int hf = tx & 1;        // which 32-col half

    const float* embB = emb + (size_t)b * Nn * Dn;

    // ---- fill: emb row -> registers, sF (swizzled fp32 frag table), sXI for i-rows ----
    float4 ereg[8];
    {
        const float4* src = reinterpret_cast<const float4*>(embB + jr * Dn + hf * 32);
        #pragma unroll
        for (int k = 0; k < 8; k++) ereg[k] = src[k];
        #pragma unroll
        for (int s = 0; s < 2; s++) {
            const int ks = 2 * hf + s;
            #pragma unroll
            for (int qq = 0; qq < 4; qq++) {
                float4 va = ereg[4 * s + (qq >> 1)];
                float4 vb = ereg[4 * s + 2 + (qq >> 1)];
                float ax = (qq & 1) ? va.z : va.x;
                float ay = (qq & 1) ? va.w : va.y;
                float bx = (qq & 1) ? vb.z : vb.x;
                float by = (qq & 1) ? vb.w : vb.y;
                *reinterpret_cast<float4*>(smem + OFF_SF + swzoff(jr, qq, ks)) =
                    make_float4(ax, ay, bx, by);
            }
        }
        // natural-order copy of the CTA's 4 i-rows
        if ((jr >> 2) == ib) {
            float4* dst = reinterpret_cast<float4*>(sXI + (jr & 3) * 72 + hf * 32);
            #pragma unroll
            for (int k = 0; k < 8; k++) dst[k] = ereg[k];
        }
    }

    // ---- fill: W row -> bf16 hi/lo splits -> sB frag table (swizzled, interleaved) ----
    {
        const float4* src = reinterpret_cast<const float4*>(wW + jr * Dn + hf * 32);
        uint32_t hu[16], lu[16];
        #pragma unroll
        for (int k = 0; k < 8; k++) {
            float4 w4 = src[k];
            split2(w4.x, w4.y, hu[2 * k],     lu[2 * k]);
            split2(w4.z, w4.w, hu[2 * k + 1], lu[2 * k + 1]);
        }
        #pragma unroll
        for (int s = 0; s < 2; s++) {
            const int ks = 2 * hf + s;
            #pragma unroll
            for (int qq = 0; qq < 4; qq++) {
                const int c0 = 8 * s + qq;
                *reinterpret_cast<uint4*>(smem + OFF_SB + swzoff(jr, qq, ks)) =
                    make_uint4(hu[c0], hu[c0 + 4], lu[c0], lu[c0 + 4]);
            }
        }
    }
    __syncthreads();

    // ---- value writes: value[b,i,jr,:] = ereg * x_i (fp32, streaming), 4 i's ----
    #pragma unroll
    for (int L = 0; L < 4; L++) {
        const int iGlob = 4 * ib + L;
        const float4* xi = reinterpret_cast<const float4*>(sXI + L * 72 + hf * 32);
        float* oV = outV + ((((size_t)b * Nn + iGlob) * Nn + jr) * Dn + hf * 32);
        #pragma unroll
        for (int k = 0; k < 8; k++) {
            float4 x4 = xi[k];
            float4 e4 = ereg[k];
            stcs4(oV + 4 * k, make_float4(e4.x * x4.x, e4.y * x4.y, e4.z * x4.z, e4.w * x4.w));
        }
    }

    // ---- GEMM passes: D[128x64] = (E*x_i) @ W^T, 3-term bf16 emulation ----
    const int jb = (wid & 1) * 32 + g;             // E row base (j) for mt tiles

    #pragma unroll
    for (int p = 0; p < 2; p++) {
        const int iLocal = 2 * p + (wid >> 1);     // this warp's i (0..3)
        const float* sXiN = sXI + iLocal * 72;

        float acc[2][8][4];
        #pragma unroll
        for (int mt = 0; mt < 2; mt++)
            #pragma unroll
            for (int nt = 0; nt < 8; nt++)
                #pragma unroll
                for (int r = 0; r < 4; r++) acc[mt][nt][r] = 0.0f;

        #pragma unroll
        for (int ks = 0; ks < 4; ks++) {
            const int kc = ks * 16 + 2 * q;
            const float2 xa = *reinterpret_cast<const float2*>(sXiN + kc);
            const float2 xb = *reinterpret_cast<const float2*>(sXiN + kc + 8);

            uint32_t ah[2][4], al[2][4];
            #pragma unroll
            for (int mt = 0; mt < 2; mt++) {
                const int j0 = jb + mt * 16;
                const float4 f0 = *reinterpret_cast<const float4*>(
                    smem + OFF_SF + swzoff(j0, q, ks));
                const float4 f1 = *reinterpret_cast<const float4*>(
                    smem + OFF_SF + swzoff(j0 + 8, q, ks));
                split2(f0.x * xa.x, f0.y * xa.y, ah[mt][0], al[mt][0]);
                split2(f1.x * xa.x, f1.y * xa.y, ah[mt][1], al[mt][1]);
                split2(f0.z * xb.x, f0.w * xb.y, ah[mt][2], al[mt][2]);
                split2(f1.z * xb.x, f1.w * xb.y, ah[mt][3], al[mt][3]);
            }
            #pragma unroll
            for (int nt = 0; nt < 8; nt++) {
                const uint4 bv = *reinterpret_cast<const uint4*>(
                    smem + OFF_SB + swzoff(nt * 8 + g, q, ks));
                uint32_t bh[2] = {bv.x, bv.y};
                uint32_t bl[2] = {bv.z, bv.w};
                #pragma unroll
                for (int mt = 0; mt < 2; mt++) {
                    mma_bf16(acc[mt][nt], ah[mt], bh);
                    mma_bf16(acc[mt][nt], ah[mt], bl);
                    mma_bf16(acc[mt][nt], al[mt], bh);
                }
            }
        }

        // ---- epilogue: bias + LeakyReLU + dot(aW) -> logits for this pass ----
        float wb0[8], wb1[8], aw0[8], aw1[8];
        #pragma unroll
        for (int nt = 0; nt < 8; nt++) {
            const int e0 = nt * 8 + 2 * q;
            wb0[nt] = sWB[e0];     wb1[nt] = sWB[e0 + 1];
            aw0[nt] = sAW[e0];     aw1[nt] = sAW[e0 + 1];
        }
        #pragma unroll
        for (int mt = 0; mt < 2; mt++) {
            #pragma unroll
            for (int half = 0; half < 2; half++) {
                float pl = 0.0f;
                #pragma unroll
                for (int nt = 0; nt < 8; nt++) {
                    float q0 = acc[mt][nt][half * 2 + 0] + wb0[nt];
                    float q1 = acc[mt][nt][half * 2 + 1] + wb1[nt];
                    q0 = (q0 >= 0.0f) ? q0 : NEG_SLOPE * q0;
                    q1 = (q1 >= 0.0f) ? q1 : NEG_SLOPE * q1;
                    pl = fmaf(aw0[nt], q0, pl);
                    pl = fmaf(aw1[nt], q1, pl);
                }
                pl += __shfl_xor_sync(0xffffffffu, pl, 1);
                pl += __shfl_xor_sync(0xffffffffu, pl, 2);
                if (q == 0) {
                    const int j = (wid & 1) * 32 + mt * 16 + half * 8 + g;
                    sLOG[iLocal * 64 + j] = pl;
                }
            }
        }
    }
    __syncthreads();

    // ---- softmax per i over 64 j's: warp w -> i = 4*ib + w ----
    {
        float v0 = sLOG[wid * 64 + lid];
        float v1 = sLOG[wid * 64 + lid + 32];
        float m = fmaxf(v0, v1);
        #pragma unroll
        for (int msk = 16; msk >= 1; msk >>= 1)
            m = fmaxf(m, __shfl_xor_sync(0xffffffffu, m, msk));
        float e0 = __expf(v0 - m);
        float e1 = __expf(v1 - m);
        float s = e0 + e1;
        #pragma unroll
        for (int msk = 16; msk >= 1; msk >>= 1)
            s += __shfl_xor_sync(0xffffffffu, s, msk);
        const float inv = 1.0f / s;
        const int iGlob = 4 * ib + wid;
        float* oa = outA + ((size_t)b * Nn + iGlob) * Nn;
        oa[lid]      = e0 * inv;
        oa[lid + 32] = e1 * inv;
    }
}

extern "C" void kernel_launch(void* const* d_in, const int* in_sizes, int n_in,
                              void* d_out, int out_size)
{
    (void)in_sizes; (void)n_in; (void)out_size;
    const float* emb = (const float*)d_in[0];
    const float* wW  = (const float*)d_in[1];
    const float* wb  = (const float*)d_in[2];
    const float* aW  = (const float*)d_in[3];
    // d_in[4] = a_b: constant shift, cancels in softmax

    float* out  = (float*)d_out;
    float* outA = out;
    float* outV = out + (size_t)Bn * Nn * Nn;

    cudaFuncSetAttribute(afm_mma, cudaFuncAttributeMaxDynamicSharedMemorySize, SMEM_TOTAL);
    dim3 grid(Nn / 4, Bn);
    afm_mma<<<grid, 128, SMEM_TOTAL>>>(emb, wW, wb, aW, outA, outV);
}